// round 3
// baseline (speedup 1.0000x reference)
#include <cuda_runtime.h>
#include <cstddef>

// ---------------- problem constants ----------------
#define NGg    8
#define NVv    400
#define NCL    1200
#define KLIT   5
#define NNG    (2 * NVv + NCL)        // 2000 nodes/graph
#define NTOT   (NGg * NNG)
#define D      128
#define LROWS  (NGg * 2 * NVv)        // 6400
#define CROWS  (NGg * NCL)            // 9600
#define NEDGE  (NGg * NCL * KLIT)     // 48000
#define EPG    (NCL * KLIT)
#define ROUNDS 26
#define ADJW   40

// ---------------- device scratch (compact layouts, ping-pong) ----------------
__device__ float d_hl[2][LROWS * D];
__device__ float d_hc[2][CROWS * D];
__device__ float d_cl[LROWS * D];
__device__ float d_cc[CROWS * D];
__device__ float d_msg[CROWS * D];    // big enough for either class
__device__ float d_agg[LROWS * D];
__device__ int   d_esrc[NEDGE];       // compact literal row per edge
__device__ int   d_adj[LROWS * ADJW];
__device__ int   d_deg[LROWS];
__device__ float d_vrow[LROWS];

// ---------------- helpers ----------------
__device__ __forceinline__ unsigned f2tf(float x) {
    unsigned r; asm("cvt.rna.tf32.f32 %0, %1;" : "=r"(r) : "f"(x)); return r;
}
__device__ __forceinline__ void mma_tf32(float c[4],
    unsigned a0, unsigned a1, unsigned a2, unsigned a3, unsigned b0, unsigned b1)
{
    asm volatile(
        "mma.sync.aligned.m16n8k8.row.col.f32.tf32.tf32.f32 "
        "{%0,%1,%2,%3}, {%4,%5,%6,%7}, {%8,%9}, {%0,%1,%2,%3};"
        : "+f"(c[0]), "+f"(c[1]), "+f"(c[2]), "+f"(c[3])
        : "r"(a0), "r"(a1), "r"(a2), "r"(a3), "r"(b0), "r"(b1));
}
__device__ __forceinline__ float sigm(float x) { return 1.f / (1.f + expf(-x)); }
__device__ __forceinline__ int fliprow(int r) {
    int local = r % (2 * NVv);
    return r - local + ((local < NVv) ? local + NVv : local - NVv);
}

// ---------------- one-time setup ----------------
__global__ void init_hc(const float* __restrict__ Lw, const float* __restrict__ Lb,
                        const float* __restrict__ Cw, const float* __restrict__ Cb,
                        float* __restrict__ hl, float* __restrict__ hc,
                        float* __restrict__ cl, float* __restrict__ cc)
{
    int r = blockIdx.x, d = threadIdx.x;
    if (r < LROWS) {
        hl[(size_t)r * D + d] = Lw[d] + Lb[d];
        cl[(size_t)r * D + d] = 0.f;
    }
    if (r < CROWS) {
        hc[(size_t)r * D + d] = Cw[d] + Cb[d];
        cc[(size_t)r * D + d] = 0.f;
    }
}

__global__ void compact_edges(const int* __restrict__ edge_src, int* __restrict__ esrc)
{
    int e = blockIdx.x * 256 + threadIdx.x;
    if (e < NEDGE) {
        int g = edge_src[e];
        esrc[e] = (g / NNG) * (2 * NVv) + (g % NNG);
    }
}

__global__ void build_adj(const int* __restrict__ esrc,
                          int* __restrict__ adj, int* __restrict__ deg)
{
    int lit = blockIdx.x * 160 + threadIdx.x;   // blocks align to graph boundaries
    int g = lit / (2 * NVv);
    const int* es = esrc + g * EPG;
    int cnt = 0;
    for (int j = 0; j < EPG; j++) {
        if (es[j] == lit) {
            if (cnt < ADJW) adj[lit * ADJW + cnt] = g * NCL + j / KLIT;
            cnt++;
        }
    }
    deg[lit] = cnt < ADJW ? cnt : ADJW;
}

// ---------------- fused MLP (NL layers of DxD), tf32 mma, BM=32, 128 threads ----------
template<int NL>
__global__ __launch_bounds__(128) void mlp_fused(
    const float* __restrict__ hin,
    const float* __restrict__ W0, const float* __restrict__ B0,
    const float* __restrict__ W1, const float* __restrict__ B1,
    const float* __restrict__ W2, const float* __restrict__ B2,
    float* __restrict__ out, int relu_last)
{
    __shared__ unsigned X[32][132];
    __shared__ unsigned Wsm[128][36];

    const int tid  = threadIdx.x;
    const int lane = tid & 31;
    const int warp = tid >> 5;
    const int grp  = lane >> 2;
    const int tig  = lane & 3;
    const int bm   = blockIdx.x * 32;

    #pragma unroll
    for (int t = 0; t < 8; t++) {
        int flat = tid + 128 * t;
        int r = flat >> 5, kb = flat & 31;
        float4 v = *(const float4*)(hin + (size_t)(bm + r) * D + kb * 4);
        X[r][kb * 4 + 0] = f2tf(v.x); X[r][kb * 4 + 1] = f2tf(v.y);
        X[r][kb * 4 + 2] = f2tf(v.z); X[r][kb * 4 + 3] = f2tf(v.w);
    }

    const float* Wl[3] = { W0, W1, W2 };
    const float* Bl[3] = { B0, B1, B2 };

    for (int l = 0; l < NL; l++) {
        float acc[2][4][4];
        #pragma unroll
        for (int mi = 0; mi < 2; mi++)
            #pragma unroll
            for (int ni = 0; ni < 4; ni++)
                #pragma unroll
                for (int u = 0; u < 4; u++) acc[mi][ni][u] = 0.f;

        const float* W = Wl[l];
        for (int ch = 0; ch < 4; ch++) {
            __syncthreads();
            #pragma unroll
            for (int t = 0; t < 8; t++) {
                int flat = tid + 128 * t;
                int n = flat >> 3, kb = flat & 7;
                float4 v = *(const float4*)(W + (size_t)n * D + ch * 32 + kb * 4);
                Wsm[n][kb * 4 + 0] = f2tf(v.x); Wsm[n][kb * 4 + 1] = f2tf(v.y);
                Wsm[n][kb * 4 + 2] = f2tf(v.z); Wsm[n][kb * 4 + 3] = f2tf(v.w);
            }
            __syncthreads();
            #pragma unroll
            for (int ks = 0; ks < 4; ks++) {
                int kk = ch * 32 + ks * 8;
                unsigned a[2][4], b[4][2];
                #pragma unroll
                for (int mi = 0; mi < 2; mi++) {
                    int r = mi * 16 + grp;
                    a[mi][0] = X[r    ][kk + tig];
                    a[mi][1] = X[r + 8][kk + tig];
                    a[mi][2] = X[r    ][kk + tig + 4];
                    a[mi][3] = X[r + 8][kk + tig + 4];
                }
                #pragma unroll
                for (int ni = 0; ni < 4; ni++) {
                    int n = warp * 32 + ni * 8 + grp;
                    b[ni][0] = Wsm[n][ks * 8 + tig];
                    b[ni][1] = Wsm[n][ks * 8 + tig + 4];
                }
                #pragma unroll
                for (int mi = 0; mi < 2; mi++)
                    #pragma unroll
                    for (int ni = 0; ni < 4; ni++)
                        mma_tf32(acc[mi][ni], a[mi][0], a[mi][1], a[mi][2], a[mi][3],
                                 b[ni][0], b[ni][1]);
            }
        }
        __syncthreads();
        const float* B = Bl[l];
        int do_relu = (l < NL - 1) || relu_last;
        #pragma unroll
        for (int mi = 0; mi < 2; mi++) {
            #pragma unroll
            for (int ni = 0; ni < 4; ni++) {
                int r0 = mi * 16 + grp;
                int c0 = warp * 32 + ni * 8 + 2 * tig;
                #pragma unroll
                for (int u = 0; u < 4; u++) {
                    int r = r0 + (u >> 1) * 8;
                    int cc = c0 + (u & 1);
                    float v = acc[mi][ni][u] + B[cc];
                    if (do_relu) v = fmaxf(v, 0.f);
                    if (l == NL - 1) out[(size_t)(bm + r) * D + cc] = v;
                    else             X[r][cc] = f2tf(v);
                }
            }
        }
    }
}

// ---------------- literal aggregation: ELL gather ----------------
__global__ void lit_agg(const float* __restrict__ msg, const int* __restrict__ adj,
                        const int* __restrict__ deg, float* __restrict__ agg)
{
    int r = blockIdx.x, d = threadIdx.x;
    int n = deg[r];
    float s = 0.f;
    for (int t = 0; t < n; t++) s += msg[(size_t)adj[r * ADJW + t] * D + d];
    agg[(size_t)r * D + d] = s;
}

// ---------------- fused gate GEMM + LSTM epilogue -----------------
// MODE 0 (clause, KTOT=256): A = [sum5 msg rows | hold(row)];  xsrc = msg, eidx = esrc
// MODE 1 (lit,    KTOT=384): A = [agg(row) | hold(flip) | hold(row)]; xsrc = agg
// Grid (M/64, 4): block y owns gate dims [y*32, y*32+32) of 128. Writes hnew, c in place.
template<int KTOT, int MODE>
__global__ __launch_bounds__(256) void gate_lstm(
    const float* __restrict__ xsrc, const int* __restrict__ eidx,
    const float* __restrict__ hold,
    const float* __restrict__ Wih, int ldwih,
    const float* __restrict__ Whh,
    const float* __restrict__ bih, const float* __restrict__ bhh,
    float* __restrict__ hnew, float* __restrict__ cst)
{
    __shared__ __align__(16) unsigned char smem[64 * 132 * 4];
    unsigned (*As)[36]    = (unsigned(*)[36])smem;
    unsigned (*Wsm)[36]   = (unsigned(*)[36])(smem + 64 * 36 * 4);
    float    (*gbuf)[132] = (float(*)[132])smem;

    const int tid  = threadIdx.x;
    const int lane = tid & 31;
    const int warp = tid >> 5;
    const int wr   = warp & 1;
    const int wc   = warp >> 1;
    const int grp  = lane >> 2;
    const int tig  = lane & 3;
    const int bm   = blockIdx.x * 64;
    const int dd0  = blockIdx.y * 32;

    float acc[2][4][4];
    #pragma unroll
    for (int mi = 0; mi < 2; mi++)
        #pragma unroll
        for (int ni = 0; ni < 4; ni++)
            #pragma unroll
            for (int u = 0; u < 4; u++) acc[mi][ni][u] = 0.f;

    const int NCH = KTOT / 32;
    for (int ch = 0; ch < NCH; ch++) {
        int k0 = ch * 32;
        __syncthreads();
        // ---- A tile 64x32 ----
        #pragma unroll
        for (int t = 0; t < 2; t++) {
            int flat = tid + 256 * t;
            int lr = flat >> 3, kb = flat & 7;
            int k = k0 + kb * 4;
            int row = bm + lr;
            float4 v;
            if (MODE == 0) {
                if (k0 < 128) {
                    const int* es = eidx + row * KLIT;
                    v = make_float4(0.f, 0.f, 0.f, 0.f);
                    #pragma unroll
                    for (int e = 0; e < KLIT; e++) {
                        float4 m = *(const float4*)(xsrc + (size_t)es[e] * D + k);
                        v.x += m.x; v.y += m.y; v.z += m.z; v.w += m.w;
                    }
                } else {
                    v = *(const float4*)(hold + (size_t)row * D + (k - 128));
                }
            } else {
                if (k0 < 128)      v = *(const float4*)(xsrc + (size_t)row * D + k);
                else if (k0 < 256) v = *(const float4*)(hold + (size_t)fliprow(row) * D + (k - 128));
                else               v = *(const float4*)(hold + (size_t)row * D + (k - 256));
            }
            As[lr][kb * 4 + 0] = f2tf(v.x); As[lr][kb * 4 + 1] = f2tf(v.y);
            As[lr][kb * 4 + 2] = f2tf(v.z); As[lr][kb * 4 + 3] = f2tf(v.w);
        }
        // ---- W tile 128x32 ----
        #pragma unroll
        for (int t = 0; t < 4; t++) {
            int flat = tid + 256 * t;
            int wrow = flat >> 3, kb = flat & 7;
            int k = k0 + kb * 4;
            int n = (wrow >> 5) * 128 + dd0 + (wrow & 31);
            const float* src = (k0 < KTOT - 128)
                ? Wih + (size_t)n * ldwih + k
                : Whh + (size_t)n * D + (k - (KTOT - 128));
            float4 v = *(const float4*)src;
            Wsm[wrow][kb * 4 + 0] = f2tf(v.x); Wsm[wrow][kb * 4 + 1] = f2tf(v.y);
            Wsm[wrow][kb * 4 + 2] = f2tf(v.z); Wsm[wrow][kb * 4 + 3] = f2tf(v.w);
        }
        __syncthreads();
        #pragma unroll
        for (int ks = 0; ks < 4; ks++) {
            unsigned a[2][4], b[4][2];
            #pragma unroll
            for (int mi = 0; mi < 2; mi++) {
                int r = wr * 32 + mi * 16 + grp;
                a[mi][0] = As[r    ][ks * 8 + tig];
                a[mi][1] = As[r + 8][ks * 8 + tig];
                a[mi][2] = As[r    ][ks * 8 + tig + 4];
                a[mi][3] = As[r + 8][ks * 8 + tig + 4];
            }
            #pragma unroll
            for (int ni = 0; ni < 4; ni++) {
                int n = wc * 32 + ni * 8 + grp;
                b[ni][0] = Wsm[n][ks * 8 + tig];
                b[ni][1] = Wsm[n][ks * 8 + tig + 4];
            }
            #pragma unroll
            for (int mi = 0; mi < 2; mi++)
                #pragma unroll
                for (int ni = 0; ni < 4; ni++)
                    mma_tf32(acc[mi][ni], a[mi][0], a[mi][1], a[mi][2], a[mi][3],
                             b[ni][0], b[ni][1]);
        }
    }

    __syncthreads();
    #pragma unroll
    for (int mi = 0; mi < 2; mi++) {
        #pragma unroll
        for (int ni = 0; ni < 4; ni++) {
            int r0 = wr * 32 + mi * 16 + grp;
            int c0 = wc * 32 + ni * 8 + 2 * tig;
            gbuf[r0    ][c0    ] = acc[mi][ni][0];
            gbuf[r0    ][c0 + 1] = acc[mi][ni][1];
            gbuf[r0 + 8][c0    ] = acc[mi][ni][2];
            gbuf[r0 + 8][c0 + 1] = acc[mi][ni][3];
        }
    }
    __syncthreads();

    int ddl = tid & 31;
    int rl0 = tid >> 5;
    int dd  = dd0 + ddl;
    float bi0 = bih[0 * 128 + dd] + bhh[0 * 128 + dd];
    float bi1 = bih[1 * 128 + dd] + bhh[1 * 128 + dd];
    float bi2 = bih[2 * 128 + dd] + bhh[2 * 128 + dd];
    float bi3 = bih[3 * 128 + dd] + bhh[3 * 128 + dd];
    #pragma unroll
    for (int it = 0; it < 8; it++) {
        int row = bm + it * 8 + rl0;
        int lrow = it * 8 + rl0;
        float gi = gbuf[lrow][0 * 32 + ddl] + bi0;
        float gf = gbuf[lrow][1 * 32 + ddl] + bi1;
        float gg = gbuf[lrow][2 * 32 + ddl] + bi2;
        float go = gbuf[lrow][3 * 32 + ddl] + bi3;
        size_t off = (size_t)row * D + dd;
        float c2 = sigm(gf) * cst[off] + sigm(gi) * tanhf(gg);
        cst[off] = c2;
        hnew[off] = sigm(go) * tanhf(c2);
    }
}

// ---------------- vote head ----------------
__global__ void vote_row(const float* __restrict__ v2, const float* __restrict__ w2,
                         const float* __restrict__ b2, float* __restrict__ vrow)
{
    int r = blockIdx.x, t = threadIdx.x;
    float p = v2[(size_t)r * D + t] * w2[t];
    #pragma unroll
    for (int s = 16; s > 0; s >>= 1) p += __shfl_down_sync(0xffffffff, p, s);
    __shared__ float ws[4];
    if ((t & 31) == 0) ws[t >> 5] = p;
    __syncthreads();
    if (t == 0) vrow[r] = ws[0] + ws[1] + ws[2] + ws[3] + b2[0];
}

__global__ void graph_mean(const float* __restrict__ vrow, const int* __restrict__ n_vars,
                           float* __restrict__ out)
{
    int g = blockIdx.x, t = threadIdx.x;
    float s = 0.f;
    for (int i = t; i < 2 * NVv; i += 256) s += vrow[g * (2 * NVv) + i];
    __shared__ float red[256];
    red[t] = s;
    __syncthreads();
    for (int st = 128; st > 0; st >>= 1) {
        if (t < st) red[t] += red[t + st];
        __syncthreads();
    }
    if (t == 0) out[g] = red[0] / (2.f * (float)n_vars[g]);
}

// ---------------- host orchestration ----------------
extern "C" void kernel_launch(void* const* d_in, const int* in_sizes, int n_in,
                              void* d_out, int out_size)
{
    const int* edge_src   = (const int*)d_in[0];
    const int* n_vars     = (const int*)d_in[6];
    const float* L_init_w = (const float*)d_in[7];
    const float* L_init_b = (const float*)d_in[8];
    const float* C_init_w = (const float*)d_in[9];
    const float* C_init_b = (const float*)d_in[10];
    const float* lmsg_w   = (const float*)d_in[11];
    const float* lmsg_b   = (const float*)d_in[12];
    const float* cmsg_w   = (const float*)d_in[13];
    const float* cmsg_b   = (const float*)d_in[14];
    const float* lu_wih   = (const float*)d_in[15];  // [512,256]
    const float* lu_whh   = (const float*)d_in[16];  // [512,128]
    const float* lu_bih   = (const float*)d_in[17];
    const float* lu_bhh   = (const float*)d_in[18];
    const float* cu_wih   = (const float*)d_in[19];  // [512,128]
    const float* cu_whh   = (const float*)d_in[20];  // [512,128]
    const float* cu_bih   = (const float*)d_in[21];
    const float* cu_bhh   = (const float*)d_in[22];
    const float* vote_w0  = (const float*)d_in[23];
    const float* vote_b0  = (const float*)d_in[24];
    const float* vote_w1  = (const float*)d_in[25];
    const float* vote_b1  = (const float*)d_in[26];
    const float* vote_w2  = (const float*)d_in[27];
    const float* vote_b2  = (const float*)d_in[28];

    float *hl0, *hl1, *hc0, *hc1, *cl, *cc, *msg, *agg, *vrow;
    int *esrc, *adj, *deg;
    cudaGetSymbolAddress((void**)&hl0,  d_hl);      hl1 = hl0 + LROWS * D;
    cudaGetSymbolAddress((void**)&hc0,  d_hc);      hc1 = hc0 + CROWS * D;
    cudaGetSymbolAddress((void**)&cl,   d_cl);
    cudaGetSymbolAddress((void**)&cc,   d_cc);
    cudaGetSymbolAddress((void**)&msg,  d_msg);
    cudaGetSymbolAddress((void**)&agg,  d_agg);
    cudaGetSymbolAddress((void**)&esrc, d_esrc);
    cudaGetSymbolAddress((void**)&adj,  d_adj);
    cudaGetSymbolAddress((void**)&deg,  d_deg);
    cudaGetSymbolAddress((void**)&vrow, d_vrow);

    compact_edges<<<(NEDGE + 255) / 256, 256>>>(edge_src, esrc);
    init_hc<<<CROWS, D>>>(L_init_w, L_init_b, C_init_w, C_init_b, hl0, hc0, cl, cc);
    build_adj<<<LROWS / 160, 160>>>(esrc, adj, deg);

    float* hls[2] = { hl0, hl1 };
    float* hcs[2] = { hc0, hc1 };

    for (int r = 0; r < ROUNDS; r++) {
        float* hlc = hls[r & 1];        // current literal h
        float* hln = hls[(r + 1) & 1];
        float* hcc = hcs[r & 1];        // current clause h
        float* hcn = hcs[(r + 1) & 1];

        // literal message MLP -> msg[0:LROWS]
        mlp_fused<3><<<LROWS / 32, 128>>>(hlc,
            lmsg_w + 0 * D * D, lmsg_b + 0 * D,
            lmsg_w + 1 * D * D, lmsg_b + 1 * D,
            lmsg_w + 2 * D * D, lmsg_b + 2 * D, msg, 0);
        // clause gate: A=[sum5 msg | hcc], LSTM epilogue -> hcn, cc
        gate_lstm<256, 0><<<dim3(CROWS / 64, 4), 256>>>(msg, esrc, hcc,
            cu_wih, D, cu_whh, cu_bih, cu_bhh, hcn, cc);
        // clause message MLP -> msg[0:CROWS]
        mlp_fused<3><<<CROWS / 32, 128>>>(hcn,
            cmsg_w + 0 * D * D, cmsg_b + 0 * D,
            cmsg_w + 1 * D * D, cmsg_b + 1 * D,
            cmsg_w + 2 * D * D, cmsg_b + 2 * D, msg, 0);
        // literal aggregation (ELL) -> agg
        lit_agg<<<LROWS, D>>>(msg, adj, deg, agg);
        // literal gate: A=[agg | hlc(flip) | hlc], LSTM epilogue -> hln, cl
        gate_lstm<384, 1><<<dim3(LROWS / 64, 4), 256>>>(agg, nullptr, hlc,
            lu_wih, 2 * D, lu_whh, lu_bih, lu_bhh, hln, cl);
    }

    // vote head on final literal h (rounds even -> ends in buffer 0)
    float* hfin = hls[ROUNDS & 1];
    mlp_fused<2><<<LROWS / 32, 128>>>(hfin,
        vote_w0, vote_b0, vote_w1, vote_b1, vote_w1, vote_b1, msg, 1);
    vote_row<<<LROWS, D>>>(msg, vote_w2, vote_b2, vrow);
    graph_mean<<<NGg, 256>>>(vrow, n_vars, (float*)d_out);

    (void)in_sizes; (void)n_in; (void)out_size;
}

// round 4
// speedup vs baseline: 1.2142x; 1.2142x over previous
#include <cuda_runtime.h>
#include <cstddef>

// ---------------- problem constants ----------------
#define NGg    8
#define NVv    400
#define NCL    1200
#define KLIT   5
#define NNG    (2 * NVv + NCL)        // 2000 nodes/graph
#define D      128
#define LROWS  (NGg * 2 * NVv)        // 6400
#define CROWS  (NGg * NCL)            // 9600
#define NEDGE  (NGg * NCL * KLIT)     // 48000
#define EPG    (NCL * KLIT)
#define ROUNDS 26
#define ADJW   40

// ---------------- device scratch (compact layouts, ping-pong) ----------------
__device__ float d_hl[2][LROWS * D];
__device__ float d_hc[2][CROWS * D];
__device__ float d_cl[LROWS * D];
__device__ float d_cc[CROWS * D];
__device__ float d_msg[CROWS * D];
__device__ float d_agg[CROWS * D];
__device__ int   d_esrc[NEDGE];
__device__ int   d_adj[LROWS * ADJW];
__device__ int   d_deg[LROWS];
__device__ float d_vrow[LROWS];

// ---------------- helpers ----------------
__device__ __forceinline__ unsigned f2tf(float x) {
    unsigned r; asm("cvt.rna.tf32.f32 %0, %1;" : "=r"(r) : "f"(x)); return r;
}
__device__ __forceinline__ void mma_tf32(float c[4],
    unsigned a0, unsigned a1, unsigned a2, unsigned a3, unsigned b0, unsigned b1)
{
    asm volatile(
        "mma.sync.aligned.m16n8k8.row.col.f32.tf32.tf32.f32 "
        "{%0,%1,%2,%3}, {%4,%5,%6,%7}, {%8,%9}, {%0,%1,%2,%3};"
        : "+f"(c[0]), "+f"(c[1]), "+f"(c[2]), "+f"(c[3])
        : "r"(a0), "r"(a1), "r"(a2), "r"(a3), "r"(b0), "r"(b1));
}
__device__ __forceinline__ float sigm(float x) { return 1.f / (1.f + expf(-x)); }
__device__ __forceinline__ int fliprow(int r) {
    int local = r % (2 * NVv);
    return r - local + ((local < NVv) ? local + NVv : local - NVv);
}

// ---------------- one-time setup ----------------
__global__ void init_hc(const float* __restrict__ Lw, const float* __restrict__ Lb,
                        const float* __restrict__ Cw, const float* __restrict__ Cb,
                        float* __restrict__ hl, float* __restrict__ hc,
                        float* __restrict__ cl, float* __restrict__ cc)
{
    int r = blockIdx.x, d = threadIdx.x;
    if (r < LROWS) {
        hl[(size_t)r * D + d] = Lw[d] + Lb[d];
        cl[(size_t)r * D + d] = 0.f;
    }
    hc[(size_t)r * D + d] = Cw[d] + Cb[d];
    cc[(size_t)r * D + d] = 0.f;
}

__global__ void compact_edges(const int* __restrict__ edge_src, int* __restrict__ esrc)
{
    int e = blockIdx.x * 256 + threadIdx.x;
    if (e < NEDGE) {
        int g = edge_src[e];
        esrc[e] = (g / NNG) * (2 * NVv) + (g % NNG);
    }
}

__global__ void build_adj(const int* __restrict__ esrc,
                          int* __restrict__ adj, int* __restrict__ deg)
{
    int lit = blockIdx.x * 160 + threadIdx.x;
    int g = lit / (2 * NVv);
    const int* es = esrc + g * EPG;
    int cnt = 0;
    for (int j = 0; j < EPG; j++) {
        if (es[j] == lit) {
            if (cnt < ADJW) adj[lit * ADJW + cnt] = g * NCL + j / KLIT;
            cnt++;
        }
    }
    deg[lit] = cnt < ADJW ? cnt : ADJW;
}

// ---------------- fused MLP: W layer resident in smem, 256 thr, BM=32 ----------
// dynamic smem: X[32][132] then Wsm[128][132] (tf32 bits)  -> 84480 bytes
template<int NL>
__global__ __launch_bounds__(256) void mlp_fused(
    const float* __restrict__ hin,
    const float* __restrict__ W0, const float* __restrict__ B0,
    const float* __restrict__ W1, const float* __restrict__ B1,
    const float* __restrict__ W2, const float* __restrict__ B2,
    float* __restrict__ out, int relu_last)
{
    extern __shared__ __align__(16) unsigned char dynsmem[];
    unsigned (*X)[132]   = (unsigned(*)[132])dynsmem;
    unsigned (*Wsm)[132] = (unsigned(*)[132])(dynsmem + 32 * 132 * 4);

    const int tid  = threadIdx.x;
    const int lane = tid & 31;
    const int warp = tid >> 5;          // 0..7 -> 16-col slice
    const int grp  = lane >> 2;
    const int tig  = lane & 3;
    const int bm   = blockIdx.x * 32;

    // load X: 32 rows x 32 float4
    #pragma unroll
    for (int t = 0; t < 4; t++) {
        int idx = tid + 256 * t;
        int r = idx >> 5, kb = idx & 31;
        float4 v = *(const float4*)(hin + (size_t)(bm + r) * D + kb * 4);
        uint4 u = make_uint4(f2tf(v.x), f2tf(v.y), f2tf(v.z), f2tf(v.w));
        *(uint4*)&X[r][kb * 4] = u;
    }

    const float* Wl[3] = { W0, W1, W2 };
    const float* Bl[3] = { B0, B1, B2 };

    for (int l = 0; l < NL; l++) {
        const float* W = Wl[l];
        #pragma unroll
        for (int t = 0; t < 16; t++) {
            int idx = tid + 256 * t;
            int n = idx >> 5, kb = idx & 31;
            float4 v = *(const float4*)(W + (size_t)n * D + kb * 4);
            uint4 u = make_uint4(f2tf(v.x), f2tf(v.y), f2tf(v.z), f2tf(v.w));
            *(uint4*)&Wsm[n][kb * 4] = u;
        }
        __syncthreads();

        float acc[2][2][4];
        #pragma unroll
        for (int mi = 0; mi < 2; mi++)
            #pragma unroll
            for (int ni = 0; ni < 2; ni++)
                #pragma unroll
                for (int u = 0; u < 4; u++) acc[mi][ni][u] = 0.f;

        #pragma unroll
        for (int ks = 0; ks < 16; ks++) {
            int kk = ks * 8;
            unsigned a[2][4], b[2][2];
            #pragma unroll
            for (int mi = 0; mi < 2; mi++) {
                int r = mi * 16 + grp;
                a[mi][0] = X[r    ][kk + tig];
                a[mi][1] = X[r + 8][kk + tig];
                a[mi][2] = X[r    ][kk + tig + 4];
                a[mi][3] = X[r + 8][kk + tig + 4];
            }
            #pragma unroll
            for (int ni = 0; ni < 2; ni++) {
                int n = warp * 16 + ni * 8 + grp;
                b[ni][0] = Wsm[n][kk + tig];
                b[ni][1] = Wsm[n][kk + tig + 4];
            }
            #pragma unroll
            for (int mi = 0; mi < 2; mi++)
                #pragma unroll
                for (int ni = 0; ni < 2; ni++)
                    mma_tf32(acc[mi][ni], a[mi][0], a[mi][1], a[mi][2], a[mi][3],
                             b[ni][0], b[ni][1]);
        }
        __syncthreads();

        const float* B = Bl[l];
        int do_relu = (l < NL - 1) || relu_last;
        #pragma unroll
        for (int mi = 0; mi < 2; mi++) {
            #pragma unroll
            for (int ni = 0; ni < 2; ni++) {
                int r0 = mi * 16 + grp;
                int c0 = warp * 16 + ni * 8 + 2 * tig;
                #pragma unroll
                for (int u = 0; u < 4; u++) {
                    int r = r0 + (u >> 1) * 8;
                    int cc = c0 + (u & 1);
                    float v = acc[mi][ni][u] + B[cc];
                    if (do_relu) v = fmaxf(v, 0.f);
                    if (l == NL - 1) out[(size_t)(bm + r) * D + cc] = v;
                    else             X[r][cc] = f2tf(v);
                }
            }
        }
    }
}

// ---------------- clause aggregation (cheap, parallel) ----------------
__global__ void clause_agg(const float* __restrict__ msg, const int* __restrict__ esrc,
                           float* __restrict__ agg)
{
    int cr = blockIdx.x, d = threadIdx.x;
    const int* es = esrc + cr * KLIT;
    float s = 0.f;
    #pragma unroll
    for (int k = 0; k < KLIT; k++) s += msg[(size_t)es[k] * D + d];
    agg[(size_t)cr * D + d] = s;
}

// ---------------- literal aggregation: ELL gather ----------------
__global__ void lit_agg(const float* __restrict__ msg, const int* __restrict__ adj,
                        const int* __restrict__ deg, float* __restrict__ agg)
{
    int r = blockIdx.x, d = threadIdx.x;
    int n = deg[r];
    float s = 0.f;
    for (int t = 0; t < n; t++) s += msg[(size_t)adj[r * ADJW + t] * D + d];
    agg[(size_t)r * D + d] = s;
}

// ---------------- fused gate GEMM (double-buffered) + LSTM epilogue -----------------
// MODE 0 (clause, KTOT=256): A = [agg(row) | hold(row)]
// MODE 1 (lit,    KTOT=384): A = [agg(row) | hold(flip) | hold(row)]
// dynamic smem: stages [As 64x36 | Ws 128x36] x2 = 55296 bytes; gbuf overlaps after final sync
template<int KTOT, int MODE>
__global__ __launch_bounds__(256) void gate_lstm(
    const float* __restrict__ agg, const float* __restrict__ hold,
    const float* __restrict__ Wih, int ldwih,
    const float* __restrict__ Whh,
    const float* __restrict__ bih, const float* __restrict__ bhh,
    float* __restrict__ hnew, float* __restrict__ cst)
{
    extern __shared__ __align__(16) unsigned char dynsmem[];
    const int STAGE = (64 * 36 + 128 * 36) * 4;    // 27648

    const int tid  = threadIdx.x;
    const int lane = tid & 31;
    const int warp = tid >> 5;
    const int wr   = warp & 1;
    const int wc   = warp >> 1;
    const int grp  = lane >> 2;
    const int tig  = lane & 3;
    const int bm   = blockIdx.x * 64;
    const int dd0  = blockIdx.y * 32;

    // per-thread load coordinates
    const int a_lr = tid >> 3;                 // rows 0..31 (+32 on t=1)
    const int a_kb = tid & 7;
    const int w_kb = tid & 7;

    float acc[2][4][4];
    #pragma unroll
    for (int mi = 0; mi < 2; mi++)
        #pragma unroll
        for (int ni = 0; ni < 4; ni++)
            #pragma unroll
            for (int u = 0; u < 4; u++) acc[mi][ni][u] = 0.f;

    // ---- A source load for chunk ch, slot t (t=0,1) ----
    auto ldA = [&](int ch, int t) -> float4 {
        int k0 = ch * 32;
        int lr = a_lr + 32 * t;
        int k  = k0 + a_kb * 4;
        int row = bm + lr;
        if (MODE == 0) {
            if (k0 < 128) return *(const float4*)(agg  + (size_t)row * D + k);
            else          return *(const float4*)(hold + (size_t)row * D + (k - 128));
        } else {
            if (k0 < 128)      return *(const float4*)(agg  + (size_t)row * D + k);
            else if (k0 < 256) return *(const float4*)(hold + (size_t)fliprow(row) * D + (k - 128));
            else               return *(const float4*)(hold + (size_t)row * D + (k - 256));
        }
    };
    auto ldW = [&](int ch, int t) -> float4 {
        int k0 = ch * 32;
        int flat = tid + 256 * t;              // 0..1023
        int wrow = flat >> 3;
        int k = k0 + w_kb * 4;
        int n = (wrow >> 5) * 128 + dd0 + (wrow & 31);
        if (k0 < KTOT - 128) return *(const float4*)(Wih + (size_t)n * ldwih + k);
        else                 return *(const float4*)(Whh + (size_t)n * D + (k - (KTOT - 128)));
    };
    auto stA = [&](int st, int t, float4 v) {
        unsigned (*As)[36] = (unsigned(*)[36])(dynsmem + st * STAGE);
        int lr = a_lr + 32 * t;
        uint4 u = make_uint4(f2tf(v.x), f2tf(v.y), f2tf(v.z), f2tf(v.w));
        *(uint4*)&As[lr][a_kb * 4] = u;
    };
    auto stW = [&](int st, int t, float4 v) {
        unsigned (*Ws)[36] = (unsigned(*)[36])(dynsmem + st * STAGE + 64 * 36 * 4);
        int flat = tid + 256 * t;
        int wrow = flat >> 3;
        uint4 u = make_uint4(f2tf(v.x), f2tf(v.y), f2tf(v.z), f2tf(v.w));
        *(uint4*)&Ws[wrow][w_kb * 4] = u;
    };

    const int NCH = KTOT / 32;
    // preload chunk 0 -> stage 0
    #pragma unroll
    for (int t = 0; t < 2; t++) stA(0, t, ldA(0, t));
    #pragma unroll
    for (int t = 0; t < 4; t++) stW(0, t, ldW(0, t));
    __syncthreads();

    for (int ch = 0; ch < NCH; ch++) {
        int st = ch & 1;
        float4 pa[2], pw[4];
        bool more = (ch + 1 < NCH);
        if (more) {
            #pragma unroll
            for (int t = 0; t < 2; t++) pa[t] = ldA(ch + 1, t);
            #pragma unroll
            for (int t = 0; t < 4; t++) pw[t] = ldW(ch + 1, t);
        }
        unsigned (*As)[36] = (unsigned(*)[36])(dynsmem + st * STAGE);
        unsigned (*Ws)[36] = (unsigned(*)[36])(dynsmem + st * STAGE + 64 * 36 * 4);
        #pragma unroll
        for (int ks = 0; ks < 4; ks++) {
            unsigned a[2][4], b[4][2];
            #pragma unroll
            for (int mi = 0; mi < 2; mi++) {
                int r = wr * 32 + mi * 16 + grp;
                a[mi][0] = As[r    ][ks * 8 + tig];
                a[mi][1] = As[r + 8][ks * 8 + tig];
                a[mi][2] = As[r    ][ks * 8 + tig + 4];
                a[mi][3] = As[r + 8][ks * 8 + tig + 4];
            }
            #pragma unroll
            for (int ni = 0; ni < 4; ni++) {
                int n = wc * 32 + ni * 8 + grp;
                b[ni][0] = Ws[n][ks * 8 + tig];
                b[ni][1] = Ws[n][ks * 8 + tig + 4];
            }
            #pragma unroll
            for (int mi = 0; mi < 2; mi++)
                #pragma unroll
                for (int ni = 0; ni < 4; ni++)
                    mma_tf32(acc[mi][ni], a[mi][0], a[mi][1], a[mi][2], a[mi][3],
                             b[ni][0], b[ni][1]);
        }
        if (more) {
            #pragma unroll
            for (int t = 0; t < 2; t++) stA(1 - st, t, pa[t]);
            #pragma unroll
            for (int t = 0; t < 4; t++) stW(1 - st, t, pw[t]);
        }
        __syncthreads();
    }

    // stage gates (gbuf overlaps the now-dead stages)
    float (*gbuf)[132] = (float(*)[132])dynsmem;
    #pragma unroll
    for (int mi = 0; mi < 2; mi++) {
        #pragma unroll
        for (int ni = 0; ni < 4; ni++) {
            int r0 = wr * 32 + mi * 16 + grp;
            int c0 = wc * 32 + ni * 8 + 2 * tig;
            gbuf[r0    ][c0    ] = acc[mi][ni][0];
            gbuf[r0    ][c0 + 1] = acc[mi][ni][1];
            gbuf[r0 + 8][c0    ] = acc[mi][ni][2];
            gbuf[r0 + 8][c0 + 1] = acc[mi][ni][3];
        }
    }
    __syncthreads();

    int ddl = tid & 31;
    int rl0 = tid >> 5;
    int dd  = dd0 + ddl;
    float bi0 = bih[0 * 128 + dd] + bhh[0 * 128 + dd];
    float bi1 = bih[1 * 128 + dd] + bhh[1 * 128 + dd];
    float bi2 = bih[2 * 128 + dd] + bhh[2 * 128 + dd];
    float bi3 = bih[3 * 128 + dd] + bhh[3 * 128 + dd];
    #pragma unroll
    for (int it = 0; it < 8; it++) {
        int lrow = it * 8 + rl0;
        int row  = bm + lrow;
        float gi = gbuf[lrow][0 * 32 + ddl] + bi0;
        float gf = gbuf[lrow][1 * 32 + ddl] + bi1;
        float gg = gbuf[lrow][2 * 32 + ddl] + bi2;
        float go = gbuf[lrow][3 * 32 + ddl] + bi3;
        size_t off = (size_t)row * D + dd;
        float c2 = sigm(gf) * cst[off] + sigm(gi) * tanhf(gg);
        cst[off] = c2;
        hnew[off] = sigm(go) * tanhf(c2);
    }
}

// ---------------- vote head ----------------
__global__ void vote_row(const float* __restrict__ v2, const float* __restrict__ w2,
                         const float* __restrict__ b2, float* __restrict__ vrow)
{
    int r = blockIdx.x, t = threadIdx.x;
    float p = v2[(size_t)r * D + t] * w2[t];
    #pragma unroll
    for (int s = 16; s > 0; s >>= 1) p += __shfl_down_sync(0xffffffff, p, s);
    __shared__ float ws[4];
    if ((t & 31) == 0) ws[t >> 5] = p;
    __syncthreads();
    if (t == 0) vrow[r] = ws[0] + ws[1] + ws[2] + ws[3] + b2[0];
}

__global__ void graph_mean(const float* __restrict__ vrow, const int* __restrict__ n_vars,
                           float* __restrict__ out)
{
    int g = blockIdx.x, t = threadIdx.x;
    float s = 0.f;
    for (int i = t; i < 2 * NVv; i += 256) s += vrow[g * (2 * NVv) + i];
    __shared__ float red[256];
    red[t] = s;
    __syncthreads();
    for (int st = 128; st > 0; st >>= 1) {
        if (t < st) red[t] += red[t + st];
        __syncthreads();
    }
    if (t == 0) out[g] = red[0] / (2.f * (float)n_vars[g]);
}

// ---------------- host orchestration ----------------
#define MLP_SMEM  ((32 * 132 + 128 * 132) * 4)
#define GATE_SMEM (2 * (64 * 36 + 128 * 36) * 4)

extern "C" void kernel_launch(void* const* d_in, const int* in_sizes, int n_in,
                              void* d_out, int out_size)
{
    const int* edge_src   = (const int*)d_in[0];
    const int* n_vars     = (const int*)d_in[6];
    const float* L_init_w = (const float*)d_in[7];
    const float* L_init_b = (const float*)d_in[8];
    const float* C_init_w = (const float*)d_in[9];
    const float* C_init_b = (const float*)d_in[10];
    const float* lmsg_w   = (const float*)d_in[11];
    const float* lmsg_b   = (const float*)d_in[12];
    const float* cmsg_w   = (const float*)d_in[13];
    const float* cmsg_b   = (const float*)d_in[14];
    const float* lu_wih   = (const float*)d_in[15];
    const float* lu_whh   = (const float*)d_in[16];
    const float* lu_bih   = (const float*)d_in[17];
    const float* lu_bhh   = (const float*)d_in[18];
    const float* cu_wih   = (const float*)d_in[19];
    const float* cu_whh   = (const float*)d_in[20];
    const float* cu_bih   = (const float*)d_in[21];
    const float* cu_bhh   = (const float*)d_in[22];
    const float* vote_w0  = (const float*)d_in[23];
    const float* vote_b0  = (const float*)d_in[24];
    const float* vote_w1  = (const float*)d_in[25];
    const float* vote_b1  = (const float*)d_in[26];
    const float* vote_w2  = (const float*)d_in[27];
    const float* vote_b2  = (const float*)d_in[28];

    float *hl0, *hl1, *hc0, *hc1, *cl, *cc, *msg, *agg, *vrow;
    int *esrc, *adj, *deg;
    cudaGetSymbolAddress((void**)&hl0,  d_hl);      hl1 = hl0 + LROWS * D;
    cudaGetSymbolAddress((void**)&hc0,  d_hc);      hc1 = hc0 + CROWS * D;
    cudaGetSymbolAddress((void**)&cl,   d_cl);
    cudaGetSymbolAddress((void**)&cc,   d_cc);
    cudaGetSymbolAddress((void**)&msg,  d_msg);
    cudaGetSymbolAddress((void**)&agg,  d_agg);
    cudaGetSymbolAddress((void**)&esrc, d_esrc);
    cudaGetSymbolAddress((void**)&adj,  d_adj);
    cudaGetSymbolAddress((void**)&deg,  d_deg);
    cudaGetSymbolAddress((void**)&vrow, d_vrow);

    cudaFuncSetAttribute(mlp_fused<3>, cudaFuncAttributeMaxDynamicSharedMemorySize, MLP_SMEM);
    cudaFuncSetAttribute(mlp_fused<2>, cudaFuncAttributeMaxDynamicSharedMemorySize, MLP_SMEM);
    cudaFuncSetAttribute(gate_lstm<256, 0>, cudaFuncAttributeMaxDynamicSharedMemorySize, GATE_SMEM);
    cudaFuncSetAttribute(gate_lstm<384, 1>, cudaFuncAttributeMaxDynamicSharedMemorySize, GATE_SMEM);

    compact_edges<<<(NEDGE + 255) / 256, 256>>>(edge_src, esrc);
    init_hc<<<CROWS, D>>>(L_init_w, L_init_b, C_init_w, C_init_b, hl0, hc0, cl, cc);
    build_adj<<<LROWS / 160, 160>>>(esrc, adj, deg);

    float* hls[2] = { hl0, hl1 };
    float* hcs[2] = { hc0, hc1 };

    for (int r = 0; r < ROUNDS; r++) {
        float* hlc = hls[r & 1];
        float* hln = hls[(r + 1) & 1];
        float* hcc = hcs[r & 1];
        float* hcn = hcs[(r + 1) & 1];

        mlp_fused<3><<<LROWS / 32, 256, MLP_SMEM>>>(hlc,
            lmsg_w + 0 * D * D, lmsg_b + 0 * D,
            lmsg_w + 1 * D * D, lmsg_b + 1 * D,
            lmsg_w + 2 * D * D, lmsg_b + 2 * D, msg, 0);
        clause_agg<<<CROWS, D>>>(msg, esrc, agg);
        gate_lstm<256, 0><<<dim3(CROWS / 64, 4), 256, GATE_SMEM>>>(agg, hcc,
            cu_wih, D, cu_whh, cu_bih, cu_bhh, hcn, cc);
        mlp_fused<3><<<CROWS / 32, 256, MLP_SMEM>>>(hcn,
            cmsg_w + 0 * D * D, cmsg_b + 0 * D,
            cmsg_w + 1 * D * D, cmsg_b + 1 * D,
            cmsg_w + 2 * D * D, cmsg_b + 2 * D, msg, 0);
        lit_agg<<<LROWS, D>>>(msg, adj, deg, agg);
        gate_lstm<384, 1><<<dim3(LROWS / 64, 4), 256, GATE_SMEM>>>(agg, hlc,
            lu_wih, 2 * D, lu_whh, lu_bih, lu_bhh, hln, cl);
    }

    float* hfin = hls[ROUNDS & 1];
    mlp_fused<2><<<LROWS / 32, 256, MLP_SMEM>>>(hfin,
        vote_w0, vote_b0, vote_w1, vote_b1, vote_w1, vote_b1, msg, 1);
    vote_row<<<LROWS, D>>>(msg, vote_w2, vote_b2, vrow);
    graph_mean<<<NGg, 256>>>(vrow, n_vars, (float*)d_out);

    (void)in_sizes; (void)n_in; (void)out_size;
}

// round 5
// speedup vs baseline: 2.0349x; 1.6759x over previous
#include <cuda_runtime.h>
#include <cuda_bf16.h>
#include <cstddef>

// ---------------- problem constants ----------------
#define NGg    8
#define NVv    400
#define NCL    1200
#define KLIT   5
#define NNG    (2 * NVv + NCL)
#define D      128
#define LROWS  (NGg * 2 * NVv)        // 6400
#define CROWS  (NGg * NCL)            // 9600
#define NEDGE  (NGg * NCL * KLIT)     // 48000
#define EPG    (NCL * KLIT)
#define ROUNDS 26
#define ADJW   40

typedef __nv_bfloat16 bf16;

// ---------------- device scratch ----------------
__device__ bf16  d_hl[2][LROWS * D];
__device__ bf16  d_hc[2][CROWS * D];
__device__ float d_cl[LROWS * D];
__device__ float d_cc[CROWS * D];
__device__ bf16  d_msg[CROWS * D];
__device__ bf16  d_agg[CROWS * D];
__device__ bf16  d_wb[524288];         // converted weights
__device__ int   d_esrc[NEDGE];
__device__ int   d_adj[LROWS * ADJW];
__device__ int   d_deg[LROWS];
__device__ float d_vrow[LROWS];

// weight offsets inside d_wb (bf16 elems)
#define WB_LMSG   0                         // 3*16384
#define WB_CMSG   49152                     // 3*16384
#define WB_CUWIH  98304                     // 512*128
#define WB_CUWHH  163840                    // 512*128
#define WB_LUWIH  229376                    // 512*256
#define WB_LUWHH  360448                    // 512*128
#define WB_VOTE0  425984                    // 16384
#define WB_VOTE1  442368                    // 16384

// ---------------- helpers ----------------
__device__ __forceinline__ void mma_bf16(float c[4],
    unsigned a0, unsigned a1, unsigned a2, unsigned a3, unsigned b0, unsigned b1)
{
    asm volatile(
        "mma.sync.aligned.m16n8k16.row.col.f32.bf16.bf16.f32 "
        "{%0,%1,%2,%3}, {%4,%5,%6,%7}, {%8,%9}, {%0,%1,%2,%3};"
        : "+f"(c[0]), "+f"(c[1]), "+f"(c[2]), "+f"(c[3])
        : "r"(a0), "r"(a1), "r"(a2), "r"(a3), "r"(b0), "r"(b1));
}
__device__ __forceinline__ void cpasync16(void* smem, const void* g)
{
    unsigned a = (unsigned)__cvta_generic_to_shared(smem);
    asm volatile("cp.async.cg.shared.global [%0], [%1], 16;" :: "r"(a), "l"(g));
}
#define CP_COMMIT() asm volatile("cp.async.commit_group;")
#define CP_WAIT0()  asm volatile("cp.async.wait_group 0;")

__device__ __forceinline__ float sigm(float x) { return 1.f / (1.f + expf(-x)); }
__device__ __forceinline__ int fliprow(int r) {
    int local = r % (2 * NVv);
    return r - local + ((local < NVv) ? local + NVv : local - NVv);
}
__device__ __forceinline__ unsigned pack_bf(float lo, float hi) {
    __nv_bfloat162 p = __floats2bfloat162_rn(lo, hi);
    return *(unsigned*)&p;
}

// ---------------- one-time setup ----------------
__global__ void cvt_w(const float* __restrict__ s, bf16* __restrict__ dst, int n)
{
    int i = blockIdx.x * 256 + threadIdx.x;
    if (i < n) dst[i] = __float2bfloat16_rn(s[i]);
}

__global__ void init_hc(const float* __restrict__ Lw, const float* __restrict__ Lb,
                        const float* __restrict__ Cw, const float* __restrict__ Cb,
                        bf16* __restrict__ hl, bf16* __restrict__ hc,
                        float* __restrict__ cl, float* __restrict__ cc)
{
    int r = blockIdx.x, d = threadIdx.x;
    if (r < LROWS) {
        hl[(size_t)r * D + d] = __float2bfloat16_rn(Lw[d] + Lb[d]);
        cl[(size_t)r * D + d] = 0.f;
    }
    hc[(size_t)r * D + d] = __float2bfloat16_rn(Cw[d] + Cb[d]);
    cc[(size_t)r * D + d] = 0.f;
}

__global__ void compact_edges(const int* __restrict__ edge_src, int* __restrict__ esrc)
{
    int e = blockIdx.x * 256 + threadIdx.x;
    if (e < NEDGE) {
        int g = edge_src[e];
        esrc[e] = (g / NNG) * (2 * NVv) + (g % NNG);
    }
}

__global__ void build_adj(const int* __restrict__ esrc,
                          int* __restrict__ adj, int* __restrict__ deg)
{
    int lit = blockIdx.x * 160 + threadIdx.x;
    int g = lit / (2 * NVv);
    const int* es = esrc + g * EPG;
    int cnt = 0;
    for (int j = 0; j < EPG; j++) {
        if (es[j] == lit) {
            if (cnt < ADJW) adj[lit * ADJW + cnt] = g * NCL + j / KLIT;
            cnt++;
        }
    }
    deg[lit] = cnt < ADJW ? cnt : ADJW;
}

// ---------------- fused MLP (bf16, cp.async W pipeline), BM=32, 256 thr -----------
// dyn smem: X[32][68] words, then Ws[2][128][68] words  -> 78336 bytes
#define MLP_SMEM ((32 * 68 + 2 * 128 * 68) * 4)
template<int NL>
__global__ __launch_bounds__(256) void mlp_fused(
    const bf16* __restrict__ hin,
    const bf16* __restrict__ W0, const float* __restrict__ B0,
    const bf16* __restrict__ W1, const float* __restrict__ B1,
    const bf16* __restrict__ W2, const float* __restrict__ B2,
    bf16* __restrict__ out, int relu_last)
{
    extern __shared__ __align__(16) unsigned char dynsmem[];
    unsigned (*X)[68] = (unsigned(*)[68])dynsmem;
    unsigned* Wbase   = (unsigned*)(dynsmem + 32 * 68 * 4);

    const int tid  = threadIdx.x;
    const int lane = tid & 31;
    const int warp = tid >> 5;          // 8 warps -> 16 cols each
    const int grp  = lane >> 2;
    const int tig  = lane & 3;
    const int bm   = blockIdx.x * 32;

    const bf16* Wl[3] = { W0, W1, W2 };
    const float* Bl[3] = { B0, B1, B2 };

    // issue async load of W layer 0 into stage 0
    {
        const bf16* W = Wl[0];
        #pragma unroll
        for (int t = 0; t < 8; t++) {
            int flat = tid + 256 * t;           // 2048 uint4
            int n = flat >> 4, kb = flat & 15;
            cpasync16(Wbase + (size_t)n * 68 + kb * 4, W + (size_t)n * D + kb * 8);
        }
        CP_COMMIT();
    }
    // load X (32 rows x 16 uint4)
    #pragma unroll
    for (int t = 0; t < 2; t++) {
        int flat = tid + 256 * t;
        int r = flat >> 4, kb = flat & 15;
        uint4 v = *(const uint4*)(hin + (size_t)(bm + r) * D + kb * 8);
        *(uint4*)&X[r][kb * 4] = v;
    }

    for (int l = 0; l < NL; l++) {
        CP_WAIT0();
        __syncthreads();
        unsigned (*Wsm)[68] = (unsigned(*)[68])(Wbase + (l & 1) * 128 * 68);
        if (l + 1 < NL) {
            unsigned* nxt = Wbase + ((l + 1) & 1) * 128 * 68;
            const bf16* W = Wl[l + 1];
            #pragma unroll
            for (int t = 0; t < 8; t++) {
                int flat = tid + 256 * t;
                int n = flat >> 4, kb = flat & 15;
                cpasync16(nxt + (size_t)n * 68 + kb * 4, W + (size_t)n * D + kb * 8);
            }
            CP_COMMIT();
        }

        float acc[2][2][4];
        #pragma unroll
        for (int mi = 0; mi < 2; mi++)
            #pragma unroll
            for (int ni = 0; ni < 2; ni++)
                #pragma unroll
                for (int u = 0; u < 4; u++) acc[mi][ni][u] = 0.f;

        #pragma unroll
        for (int ks = 0; ks < 8; ks++) {     // k16 steps
            int kk = ks * 8;
            unsigned a[2][4], b[2][2];
            #pragma unroll
            for (int mi = 0; mi < 2; mi++) {
                int r = mi * 16 + grp;
                a[mi][0] = X[r    ][kk + tig];
                a[mi][1] = X[r + 8][kk + tig];
                a[mi][2] = X[r    ][kk + tig + 4];
                a[mi][3] = X[r + 8][kk + tig + 4];
            }
            #pragma unroll
            for (int ni = 0; ni < 2; ni++) {
                int n = warp * 16 + ni * 8 + grp;
                b[ni][0] = Wsm[n][kk + tig];
                b[ni][1] = Wsm[n][kk + tig + 4];
            }
            #pragma unroll
            for (int mi = 0; mi < 2; mi++)
                #pragma unroll
                for (int ni = 0; ni < 2; ni++)
                    mma_bf16(acc[mi][ni], a[mi][0], a[mi][1], a[mi][2], a[mi][3],
                             b[ni][0], b[ni][1]);
        }
        __syncthreads();

        const float* B = Bl[l];
        int do_relu = (l < NL - 1) || relu_last;
        #pragma unroll
        for (int mi = 0; mi < 2; mi++) {
            #pragma unroll
            for (int ni = 0; ni < 2; ni++) {
                int r0 = mi * 16 + grp;
                int c0 = warp * 16 + ni * 8 + 2 * tig;   // even
                #pragma unroll
                for (int h = 0; h < 2; h++) {            // row sub (acc u pairs)
                    int r = r0 + h * 8;
                    float v0 = acc[mi][ni][h * 2 + 0] + B[c0];
                    float v1 = acc[mi][ni][h * 2 + 1] + B[c0 + 1];
                    if (do_relu) { v0 = fmaxf(v0, 0.f); v1 = fmaxf(v1, 0.f); }
                    unsigned p = pack_bf(v0, v1);
                    if (l == NL - 1)
                        *(unsigned*)(out + (size_t)(bm + r) * D + c0) = p;
                    else
                        X[r][c0 >> 1] = p;
                }
            }
        }
        // X rewritten; next layer waits+syncs at loop top
    }
}

// ---------------- clause aggregation ----------------
__global__ void clause_agg(const bf16* __restrict__ msg, const int* __restrict__ esrc,
                           bf16* __restrict__ agg)
{
    int cr = blockIdx.x, d = threadIdx.x;
    const int* es = esrc + cr * KLIT;
    float s = 0.f;
    #pragma unroll
    for (int k = 0; k < KLIT; k++) s += __bfloat162float(msg[(size_t)es[k] * D + d]);
    agg[(size_t)cr * D + d] = __float2bfloat16_rn(s);
}

// ---------------- literal aggregation (ELL) ----------------
__global__ void lit_agg(const bf16* __restrict__ msg, const int* __restrict__ adj,
                        const int* __restrict__ deg, bf16* __restrict__ agg)
{
    int r = blockIdx.x, d = threadIdx.x;
    int n = deg[r];
    float s = 0.f;
    for (int t = 0; t < n; t++)
        s += __bfloat162float(msg[(size_t)adj[r * ADJW + t] * D + d]);
    agg[(size_t)r * D + d] = __float2bfloat16_rn(s);
}

// ---------------- fused gate GEMM (bf16, double-buffered) + LSTM epilogue ----------
// MODE 0 (clause, KTOT=256): A = [agg | hold]
// MODE 1 (lit,    KTOT=384): A = [agg | hold(flip) | hold]
// k-chunks of 64 elems; stages: As[64][36] + Ws[128][36] words
#define GATE_STAGE ((64 * 36 + 128 * 36) * 4)
#define GATE_SMEM  (2 * GATE_STAGE)
template<int KTOT, int MODE>
__global__ __launch_bounds__(256) void gate_lstm(
    const bf16* __restrict__ agg, const bf16* __restrict__ hold,
    const bf16* __restrict__ Wih, int ldwih,
    const bf16* __restrict__ Whh,
    const float* __restrict__ bih, const float* __restrict__ bhh,
    bf16* __restrict__ hnew, float* __restrict__ cst)
{
    extern __shared__ __align__(16) unsigned char dynsmem[];

    const int tid  = threadIdx.x;
    const int lane = tid & 31;
    const int warp = tid >> 5;
    const int wr   = warp & 1;
    const int wc   = warp >> 1;
    const int grp  = lane >> 2;
    const int tig  = lane & 3;
    const int bm   = blockIdx.x * 64;
    const int dd0  = blockIdx.y * 32;

    float acc[2][4][4];
    #pragma unroll
    for (int mi = 0; mi < 2; mi++)
        #pragma unroll
        for (int ni = 0; ni < 4; ni++)
            #pragma unroll
            for (int u = 0; u < 4; u++) acc[mi][ni][u] = 0.f;

    auto ldA = [&](int ch, int t) -> uint4 {
        int k0 = ch * 64;
        int flat = tid + 256 * t;
        int lr = flat >> 3, kb = flat & 7;
        int row = bm + lr;
        int k = k0 + kb * 8;
        if (MODE == 0) {
            if (k0 < 128) return *(const uint4*)(agg  + (size_t)row * D + k);
            else          return *(const uint4*)(hold + (size_t)row * D + (k - 128));
        } else {
            if (k0 < 128)      return *(const uint4*)(agg  + (size_t)row * D + k);
            else if (k0 < 256) return *(const uint4*)(hold + (size_t)fliprow(row) * D + (k - 128));
            else               return *(const uint4*)(hold + (size_t)row * D + (k - 256));
        }
    };
    auto ldW = [&](int ch, int t) -> uint4 {
        int k0 = ch * 64;
        int flat = tid + 256 * t;
        int wrow = flat >> 3, kb = flat & 7;
        int n = (wrow >> 5) * 128 + dd0 + (wrow & 31);
        int k = k0 + kb * 8;
        if (k0 < KTOT - 128) return *(const uint4*)(Wih + (size_t)n * ldwih + k);
        else                 return *(const uint4*)(Whh + (size_t)n * D + (k - (KTOT - 128)));
    };
    auto stA = [&](int st, int t, uint4 v) {
        unsigned (*As)[36] = (unsigned(*)[36])(dynsmem + st * GATE_STAGE);
        int flat = tid + 256 * t;
        int lr = flat >> 3, kb = flat & 7;
        *(uint4*)&As[lr][kb * 4] = v;
    };
    auto stW = [&](int st, int t, uint4 v) {
        unsigned (*Ws)[36] = (unsigned(*)[36])(dynsmem + st * GATE_STAGE + 64 * 36 * 4);
        int flat = tid + 256 * t;
        int wrow = flat >> 3, kb = flat & 7;
        *(uint4*)&Ws[wrow][kb * 4] = v;
    };

    const int NCH = KTOT / 64;
    #pragma unroll
    for (int t = 0; t < 2; t++) stA(0, t, ldA(0, t));
    #pragma unroll
    for (int t = 0; t < 4; t++) stW(0, t, ldW(0, t));
    __syncthreads();

    for (int ch = 0; ch < NCH; ch++) {
        int st = ch & 1;
        uint4 pa[2], pw[4];
        bool more = (ch + 1 < NCH);
        if (more) {
            #pragma unroll
            for (int t = 0; t < 2; t++) pa[t] = ldA(ch + 1, t);
            #pragma unroll
            for (int t = 0; t < 4; t++) pw[t] = ldW(ch + 1, t);
        }
        unsigned (*As)[36] = (unsigned(*)[36])(dynsmem + st * GATE_STAGE);
        unsigned (*Ws)[36] = (unsigned(*)[36])(dynsmem + st * GATE_STAGE + 64 * 36 * 4);
        #pragma unroll
        for (int ks = 0; ks < 4; ks++) {      // 4 x k16 = 64
            unsigned a[2][4], b[4][2];
            #pragma unroll
            for (int mi = 0; mi < 2; mi++) {
                int r = wr * 32 + mi * 16 + grp;
                a[mi][0] = As[r    ][ks * 8 + tig];
                a[mi][1] = As[r + 8][ks * 8 + tig];
                a[mi][2] = As[r    ][ks * 8 + tig + 4];
                a[mi][3] = As[r + 8][ks * 8 + tig + 4];
            }
            #pragma unroll
            for (int ni = 0; ni < 4; ni++) {
                int n = wc * 32 + ni * 8 + grp;
                b[ni][0] = Ws[n][ks * 8 + tig];
                b[ni][1] = Ws[n][ks * 8 + tig + 4];
            }
            #pragma unroll
            for (int mi = 0; mi < 2; mi++)
                #pragma unroll
                for (int ni = 0; ni < 4; ni++)
                    mma_bf16(acc[mi][ni], a[mi][0], a[mi][1], a[mi][2], a[mi][3],
                             b[ni][0], b[ni][1]);
        }
        if (more) {
            #pragma unroll
            for (int t = 0; t < 2; t++) stA(1 - st, t, pa[t]);
            #pragma unroll
            for (int t = 0; t < 4; t++) stW(1 - st, t, pw[t]);
        }
        __syncthreads();
    }

    float (*gbuf)[132] = (float(*)[132])dynsmem;
    #pragma unroll
    for (int mi = 0; mi < 2; mi++) {
        #pragma unroll
        for (int ni = 0; ni < 4; ni++) {
            int r0 = wr * 32 + mi * 16 + grp;
            int c0 = wc * 32 + ni * 8 + 2 * tig;
            gbuf[r0    ][c0    ] = acc[mi][ni][0];
            gbuf[r0    ][c0 + 1] = acc[mi][ni][1];
            gbuf[r0 + 8][c0    ] = acc[mi][ni][2];
            gbuf[r0 + 8][c0 + 1] = acc[mi][ni][3];
        }
    }
    __syncthreads();

    int ddl = tid & 31;
    int rl0 = tid >> 5;
    int dd  = dd0 + ddl;
    float bi0 = bih[0 * 128 + dd] + bhh[0 * 128 + dd];
    float bi1 = bih[1 * 128 + dd] + bhh[1 * 128 + dd];
    float bi2 = bih[2 * 128 + dd] + bhh[2 * 128 + dd];
    float bi3 = bih[3 * 128 + dd] + bhh[3 * 128 + dd];
    #pragma unroll
    for (int it = 0; it < 8; it++) {
        int lrow = it * 8 + rl0;
        int row  = bm + lrow;
        float gi = gbuf[lrow][0 * 32 + ddl] + bi0;
        float gf = gbuf[lrow][1 * 32 + ddl] + bi1;
        float gg = gbuf[lrow][2 * 32 + ddl] + bi2;
        float go = gbuf[lrow][3 * 32 + ddl] + bi3;
        size_t off = (size_t)row * D + dd;
        float c2 = sigm(gf) * cst[off] + sigm(gi) * tanhf(gg);
        cst[off] = c2;
        hnew[off] = __float2bfloat16_rn(sigm(go) * tanhf(c2));
    }
}

// ---------------- vote head ----------------
__global__ void vote_row(const bf16* __restrict__ v2, const float* __restrict__ w2,
                         const float* __restrict__ b2, float* __restrict__ vrow)
{
    int r = blockIdx.x, t = threadIdx.x;
    float p = __bfloat162float(v2[(size_t)r * D + t]) * w2[t];
    #pragma unroll
    for (int s = 16; s > 0; s >>= 1) p += __shfl_down_sync(0xffffffff, p, s);
    __shared__ float ws[4];
    if ((t & 31) == 0) ws[t >> 5] = p;
    __syncthreads();
    if (t == 0) vrow[r] = ws[0] + ws[1] + ws[2] + ws[3] + b2[0];
}

__global__ void graph_mean(const float* __restrict__ vrow, const int* __restrict__ n_vars,
                           float* __restrict__ out)
{
    int g = blockIdx.x, t = threadIdx.x;
    float s = 0.f;
    for (int i = t; i < 2 * NVv; i += 256) s += vrow[g * (2 * NVv) + i];
    __shared__ float red[256];
    red[t] = s;
    __syncthreads();
    for (int st = 128; st > 0; st >>= 1) {
        if (t < st) red[t] += red[t + st];
        __syncthreads();
    }
    if (t == 0) out[g] = red[0] / (2.f * (float)n_vars[g]);
}

// ---------------- host orchestration ----------------
extern "C" void kernel_launch(void* const* d_in, const int* in_sizes, int n_in,
                              void* d_out, int out_size)
{
    const int* edge_src   = (const int*)d_in[0];
    const int* n_vars     = (const int*)d_in[6];
    const float* L_init_w = (const float*)d_in[7];
    const float* L_init_b = (const float*)d_in[8];
    const float* C_init_w = (const float*)d_in[9];
    const float* C_init_b = (const float*)d_in[10];
    const float* lmsg_w   = (const float*)d_in[11];
    const float* lmsg_b   = (const float*)d_in[12];
    const float* cmsg_w   = (const float*)d_in[13];
    const float* cmsg_b   = (const float*)d_in[14];
    const float* lu_wih   = (const float*)d_in[15];
    const float* lu_whh   = (const float*)d_in[16];
    const float* lu_bih   = (const float*)d_in[17];
    const float* lu_bhh   = (const float*)d_in[18];
    const float* cu_wih   = (const float*)d_in[19];
    const float* cu_whh   = (const float*)d_in[20];
    const float* cu_bih   = (const float*)d_in[21];
    const float* cu_bhh   = (const float*)d_in[22];
    const float* vote_w0  = (const float*)d_in[23];
    const float* vote_b0  = (const float*)d_in[24];
    const float* vote_w1  = (const float*)d_in[25];
    const float* vote_b1  = (const float*)d_in[26];
    const float* vote_w2  = (const float*)d_in[27];
    const float* vote_b2  = (const float*)d_in[28];

    bf16 *hl0, *hl1, *hc0, *hc1, *msg, *agg, *wb;
    float *cl, *cc, *vrow;
    int *esrc, *adj, *deg;
    cudaGetSymbolAddress((void**)&hl0,  d_hl);      hl1 = hl0 + LROWS * D;
    cudaGetSymbolAddress((void**)&hc0,  d_hc);      hc1 = hc0 + CROWS * D;
    cudaGetSymbolAddress((void**)&cl,   d_cl);
    cudaGetSymbolAddress((void**)&cc,   d_cc);
    cudaGetSymbolAddress((void**)&msg,  d_msg);
    cudaGetSymbolAddress((void**)&agg,  d_agg);
    cudaGetSymbolAddress((void**)&wb,   d_wb);
    cudaGetSymbolAddress((void**)&esrc, d_esrc);
    cudaGetSymbolAddress((void**)&adj,  d_adj);
    cudaGetSymbolAddress((void**)&deg,  d_deg);
    cudaGetSymbolAddress((void**)&vrow, d_vrow);

    cudaFuncSetAttribute(mlp_fused<3>, cudaFuncAttributeMaxDynamicSharedMemorySize, MLP_SMEM);
    cudaFuncSetAttribute(mlp_fused<2>, cudaFuncAttributeMaxDynamicSharedMemorySize, MLP_SMEM);
    cudaFuncSetAttribute(gate_lstm<256, 0>, cudaFuncAttributeMaxDynamicSharedMemorySize, GATE_SMEM);
    cudaFuncSetAttribute(gate_lstm<384, 1>, cudaFuncAttributeMaxDynamicSharedMemorySize, GATE_SMEM);

    // one-time weight conversion to bf16
    cvt_w<<<(3 * 16384 + 255) / 256, 256>>>(lmsg_w,  wb + WB_LMSG,  3 * 16384);
    cvt_w<<<(3 * 16384 + 255) / 256, 256>>>(cmsg_w,  wb + WB_CMSG,  3 * 16384);
    cvt_w<<<(65536 + 255) / 256, 256>>>(cu_wih, wb + WB_CUWIH, 65536);
    cvt_w<<<(65536 + 255) / 256, 256>>>(cu_whh, wb + WB_CUWHH, 65536);
    cvt_w<<<(131072 + 255) / 256, 256>>>(lu_wih, wb + WB_LUWIH, 131072);
    cvt_w<<<(65536 + 255) / 256, 256>>>(lu_whh, wb + WB_LUWHH, 65536);
    cvt_w<<<(16384 + 255) / 256, 256>>>(vote_w0, wb + WB_VOTE0, 16384);
    cvt_w<<<(16384 + 255) / 256, 256>>>(vote_w1, wb + WB_VOTE1, 16384);

    compact_edges<<<(NEDGE + 255) / 256, 256>>>(edge_src, esrc);
    init_hc<<<CROWS, D>>>(L_init_w, L_init_b, C_init_w, C_init_b, hl0, hc0, cl, cc);
    build_adj<<<LROWS / 160, 160>>>(esrc, adj, deg);

    bf16* hls[2] = { hl0, hl1 };
    bf16* hcs[2] = { hc0, hc1 };

    for (int r = 0; r < ROUNDS; r++) {
        bf16* hlc = hls[r & 1];
        bf16* hln = hls[(r + 1) & 1];
        bf16* hcc = hcs[r & 1];
        bf16* hcn = hcs[(r + 1) & 1];

        mlp_fused<3><<<LROWS / 32, 256, MLP_SMEM>>>(hlc,
            wb + WB_LMSG + 0 * D * D, lmsg_b + 0 * D,
            wb + WB_LMSG + 1 * D * D, lmsg_b + 1 * D,
            wb + WB_LMSG + 2 * D * D, lmsg_b + 2 * D, msg, 0);
        clause_agg<<<CROWS, D>>>(msg, esrc, agg);
        gate_lstm<256, 0><<<dim3(CROWS / 64, 4), 256, GATE_SMEM>>>(agg, hcc,
            wb + WB_CUWIH, D, wb + WB_CUWHH, cu_bih, cu_bhh, hcn, cc);
        mlp_fused<3><<<CROWS / 32, 256, MLP_SMEM>>>(hcn,
            wb + WB_CMSG + 0 * D * D, cmsg_b + 0 * D,
            wb + WB_CMSG + 1 * D * D, cmsg_b + 1 * D,
            wb + WB_CMSG + 2 * D * D, cmsg_b + 2 * D, msg, 0);
        lit_agg<<<LROWS, D>>>(msg, adj, deg, agg);
        gate_lstm<384, 1><<<dim3(LROWS / 64, 4), 256, GATE_SMEM>>>(agg, hlc,
            wb + WB_LUWIH, 2 * D, wb + WB_LUWHH, lu_bih, lu_bhh, hln, cl);
    }

    bf16* hfin = hls[ROUNDS & 1];
    mlp_fused<2><<<LROWS / 32, 256, MLP_SMEM>>>(hfin,
        wb + WB_VOTE0, vote_b0, wb + WB_VOTE1, vote_b1, wb + WB_VOTE1, vote_b1, msg, 1);
    vote_row<<<LROWS, D>>>(msg, vote_w2, vote_b2, vrow);
    graph_mean<<<NGg, 256>>>(vrow, n_vars, (float*)d_out);

    (void)in_sizes; (void)n_in; (void)out_size;
}